// round 10
// baseline (speedup 1.0000x reference)
#include <cuda_runtime.h>

// (4,4,3,192,192) fp32 -> (4,4,2,192,192): per-patch KDE entropies (R=3, h=0.1).
// R10: all-scalar (sm_100a has no packed f32x2 ALU — packed ops were emulated),
// dot-form distances (u_i.u_j + nt_i + nt_j, 4 fma-ops/pair), FMA-fused joint
// accumulation. R9 skeleton: staged smem loads, lane-split frames, fused shuffle.

#define WW  192
#define HW  (192 * 192)

#define CM     (-1.9537149f)      // log9 + 1.5*ln(2*pi*0.01)  (C=3 marginal)
#define CJ     (-6.1046541f)      // log9 + 3.0*ln(2*pi*0.01)  (C=6 joint)
#define LN2_9  (0.0770163534f)    // ln(2)/9
#define PSC2   (12.0112240f)      // sqrt(100*log2(e)): exp(-50*d2)=ex2(u.u' + nt + nt')

// sm[frame][chan*3+row][40]: pad 40 -> frame stride 360 = 8 (mod 32):
//   compute LDS bank = 8*sf + sub  -> all 32 lanes distinct (conflict-free)
//   store  STS bank  = lane        -> conflict-free
#define FSTRIDE 360    // 9 * 40
#define RSTRIDE 40

static __device__ __forceinline__ float fast_ex2(float x)
{ float r; asm("ex2.approx.ftz.f32 %0, %1;" : "=f"(r) : "f"(x)); return r; }

static __device__ __forceinline__ float fast_lg2(float x)
{ float r; asm("lg2.approx.f32 %0, %1;" : "=f"(r) : "f"(x)); return r; }

static __device__ __forceinline__ float prod9(const float s[9])
{
    return ((s[0] * s[1]) * (s[2] * s[3])) *
           ((s[4] * s[5]) * (s[6] * s[7])) * s[8];
}

__global__ void __launch_bounds__(128)
je10_kernel(const float* __restrict__ in, float* __restrict__ out)
{
    __shared__ float sm[4 * FSTRIDE];

    int tid  = threadIdx.x;
    int lane = tid & 31;
    int warp = tid >> 5;
    int sf   = lane & 3;          // frame handled by this lane (compute phase)
    int sub  = lane >> 2;         // patch slot within warp
    int lp   = warp * 8 + sub;    // local patch col within block, 0..31

    int x0 = blockIdx.x * 32;     // block's first patch col
    int y  = blockIdx.y;          // patch row 0..189
    int n  = blockIdx.z;

    // ---- cooperative staged load: warp w loads frame w (9 rows of 34 px) ----
    {
        const float* gb = in + ((size_t)(n * 4 + warp) * 3) * HW + y * WW + x0;
        float* sb = sm + warp * FSTRIDE;
        #pragma unroll
        for (int it = 0; it < 9; ++it) {
            const int cc = it / 3, r = it % 3;          // compile-time
            sb[it * RSTRIDE + lane] = gb[cc * HW + r * WW + lane] * PSC2;
        }
        if (lane < 2) {                                  // tail cols 32,33
            int gx = x0 + 32 + lane;
            int cl = (gx > 191) ? (191 - x0) : (32 + lane);
            #pragma unroll
            for (int it = 0; it < 9; ++it) {
                const int cc = it / 3, r = it % 3;
                sb[it * RSTRIDE + 32 + lane] = gb[cc * HW + r * WW + cl] * PSC2;
            }
        }
    }
    __syncthreads();

    // ---- read this lane's 3x3 patch of its frame + per-pixel -0.5|u|^2 ----
    float u[9][3], nt[9];
    {
        const float* sb = sm + sf * FSTRIDE + lp;
        #pragma unroll
        for (int c = 0; c < 3; ++c)
            #pragma unroll
            for (int dy = 0; dy < 3; ++dy)
                #pragma unroll
                for (int dx = 0; dx < 3; ++dx)
                    u[dy * 3 + dx][c] = sb[(c * 3 + dy) * RSTRIDE + dx];
        #pragma unroll
        for (int p = 0; p < 9; ++p) {
            float t = u[p][0] * u[p][0];
            t = fmaf(u[p][1], u[p][1], t);
            t = fmaf(u[p][2], u[p][2], t);
            nt[p] = -0.5f * t;
        }
    }

    // Shuffle source: next frame's lane (same patch); frame 3 pairs with itself.
    int src = (sf == 3) ? lane : (lane + 1);

    // ---- fused pass: 36 exps, immediate shuffle, scalar (marg, joint) acc ----
    float s[9], sj[9];
    #pragma unroll
    for (int i = 0; i < 9; ++i) { s[i] = 1.0f; sj[i] = 1.0f; }  // diag exp(0)

    #pragma unroll
    for (int i = 0; i < 9; ++i) {
        #pragma unroll
        for (int j = i + 1; j < 9; ++j) {
            float a = fmaf(u[i][0], u[j][0], nt[i]);
            a = fmaf(u[i][1], u[j][1], a);
            a = fmaf(u[i][2], u[j][2], a);
            a = a + nt[j];
            float ee = fast_ex2(a);                        // exp(-50*d2)
            float en = __shfl_sync(0xffffffffu, ee, src);  // lockstep: same pair
            s[i]  += ee;
            s[j]  += ee;
            sj[i] = fmaf(ee, en, sj[i]);                   // joint = ee*en, fused
            sj[j] = fmaf(ee, en, sj[j]);
        }
    }

    float hm = CM - LN2_9 * fast_lg2(prod9(s));
    float hj = CJ - LN2_9 * fast_lg2(prod9(sj));

    // ---- stores: this thread owns channels 2*sf, 2*sf+1 of batch n ----
    int x = x0 + lp;
    if (x < 190) {
        float* ob = out + ((size_t)(n * 4 + sf) * 2) * HW;
        int oofs = (y + 1) * WW + (x + 1);
        ob[oofs]      = hm;
        ob[HW + oofs] = hj;

        // border ring zeroing (output is poisoned 0xAA)
        if (y == 0)   { ob[x + 1] = 0.0f;            ob[HW + x + 1] = 0.0f; }
        if (y == 189) { ob[191*WW + x + 1] = 0.0f;   ob[HW + 191*WW + x + 1] = 0.0f; }
        if (x == 0) {
            ob[(y + 1) * WW] = 0.0f;      ob[HW + (y + 1) * WW] = 0.0f;
            if (y == 0)   { ob[0] = 0.0f;            ob[HW] = 0.0f; }
            if (y == 189) { ob[191*WW] = 0.0f;       ob[HW + 191*WW] = 0.0f; }
        }
        if (x == 189) {
            ob[(y + 1) * WW + 191] = 0.0f; ob[HW + (y + 1) * WW + 191] = 0.0f;
            if (y == 0)   { ob[191] = 0.0f;          ob[HW + 191] = 0.0f; }
            if (y == 189) { ob[191*WW + 191] = 0.0f; ob[HW + 191*WW + 191] = 0.0f; }
        }
    }
}

extern "C" void kernel_launch(void* const* d_in, const int* in_sizes, int n_in,
                              void* d_out, int out_size)
{
    dim3 blk(128, 1, 1);
    dim3 grd(6, 190, 4);   // 6 blocks x 32 patch cols = 192 (190 valid); 190 rows; 4 batches
    je10_kernel<<<grd, blk>>>((const float*)d_in[0], (float*)d_out);
}